// round 1
// baseline (speedup 1.0000x reference)
#include <cuda_runtime.h>

// ListNet ranking loss, GB300.
// pass1: per-date histogram of (sum exp(p), count, labelsum) via single packed
//        64-bit RED into per-block replica slabs.
// reduce: fold replicas, build float2 {w=1/denomT (0 if invalid), logDenomP}.
// pass2: per-row  w * (l ? e^5 : 1) * (logDenomP[d] - p), block-reduced into a
//        double accumulator. finalize divides by n_valid.

#define NDATES 4096
#define NREP   304          // 2 blocks per SM (152 SMs)
#define T1     512
#define E5f    148.4131591025766f
#define E5M1f  147.4131591025766f

__device__ unsigned long long g_part[(size_t)NREP * NDATES];  // ~10MB scratch
__device__ float2 g_tab[NDATES];   // {w, logDenomP}
__device__ double g_ce;
__device__ int    g_nvalid;
__device__ int    g_is64_dates, g_is64_labels;

// ---------------------------------------------------------------- detect ----
// JAX may deliver int64 or (x64-disabled) int32 for labels/dates. Values are
// small and non-negative, so if int64 every odd 32-bit word is zero.
__global__ void k_detect(const unsigned int* __restrict__ labels,
                         const unsigned int* __restrict__ dates) {
    if (threadIdx.x == 0) {
        int d64 = 1, l64 = 1;
#pragma unroll 1
        for (int i = 1; i < 256; i += 2) {
            if (dates[i])  d64 = 0;
            if (labels[i]) l64 = 0;
        }
        g_is64_dates  = d64;
        g_is64_labels = l64;
    }
}

// ------------------------------------------------------------------ init ----
__global__ void k_init() {
    size_t i      = (size_t)blockIdx.x * blockDim.x + threadIdx.x;
    size_t stride = (size_t)gridDim.x * blockDim.x;
    size_t tot    = (size_t)NREP * NDATES;
    for (; i < tot; i += stride) g_part[i] = 0ull;
    if (blockIdx.x == 0 && threadIdx.x == 0) { g_ce = 0.0; g_nvalid = 0; }
}

// ----------------------------------------------------------------- pass1 ----
// One packed u64 RED per row into this block's replica:
//   bits [0,33)  : exp(p) in 16.16 fixed point   (block partial < 2^33)
//   bits [33,48) : count                          (block partial <= 27648)
//   bits [48,63) : labelsum
__global__ void __launch_bounds__(T1) k_pass1(
        const float4* __restrict__ scores,
        const void*   __restrict__ labels,
        const void*   __restrict__ dates,
        long long pairs) {
    const int is64d = g_is64_dates, is64l = g_is64_labels;
    unsigned long long* part = g_part + (size_t)blockIdx.x * NDATES;
    long long t      = (long long)blockIdx.x * blockDim.x + threadIdx.x;
    long long stride = (long long)gridDim.x * blockDim.x;
    for (long long k = t; k < pairs; k += stride) {
        float4 s = scores[k];                      // rows 2k, 2k+1
        int d0, d1, l0, l1;
        if (is64d) { longlong2 v = ((const longlong2*)dates)[k];  d0 = (int)v.x; d1 = (int)v.y; }
        else       { int2      v = ((const int2*)dates)[k];       d0 = v.x;      d1 = v.y;      }
        if (is64l) { longlong2 v = ((const longlong2*)labels)[k]; l0 = (int)v.x; l1 = (int)v.y; }
        else       { int2      v = ((const int2*)labels)[k];      l0 = v.x;      l1 = v.y;      }

        float p0 = __fdividef(1.f, 1.f + __expf(s.x - s.y));   // sigmoid(s1-s0)
        float p1 = __fdividef(1.f, 1.f + __expf(s.z - s.w));
        unsigned long long a0 =
            (unsigned long long)__float2uint_rn(__expf(p0) * 65536.f)
            + (1ull << 33) + ((unsigned long long)(l0 != 0) << 48);
        unsigned long long a1 =
            (unsigned long long)__float2uint_rn(__expf(p1) * 65536.f)
            + (1ull << 33) + ((unsigned long long)(l1 != 0) << 48);
        atomicAdd(part + d0, a0);   // RED.E.ADD.64 (result unused)
        atomicAdd(part + d1, a1);
    }
}

// ---------------------------------------------------------------- reduce ----
__global__ void k_reduce() {
    int d = blockIdx.x * blockDim.x + threadIdx.x;   // 4096 threads exactly
    unsigned long long epsum = 0;
    unsigned int cnt = 0, lab = 0;
#pragma unroll 4
    for (int r = 0; r < NREP; r++) {
        unsigned long long v = g_part[(size_t)r * NDATES + d];
        epsum += v & ((1ull << 33) - 1);
        cnt   += (unsigned int)((v >> 33) & 0x7FFFu);
        lab   += (unsigned int)(v >> 48);
    }
    bool valid = (cnt >= 2);
    float w  = valid ? __fdividef(1.f, (float)cnt + (float)lab * E5M1f) : 0.f;
    float ld = valid ? __logf((float)epsum * (1.f / 65536.f)) : 0.f;
    g_tab[d] = make_float2(w, ld);
    unsigned int m = __ballot_sync(0xffffffffu, valid);
    if ((threadIdx.x & 31) == 0) atomicAdd(&g_nvalid, __popc(m));
}

// ----------------------------------------------------------------- pass2 ----
__global__ void __launch_bounds__(T1) k_pass2(
        const float4* __restrict__ scores,
        const void*   __restrict__ labels,
        const void*   __restrict__ dates,
        long long pairs) {
    __shared__ float2 tab[NDATES];                 // 32KB: keep table in SMEM
    for (int i = threadIdx.x; i < NDATES; i += blockDim.x) tab[i] = g_tab[i];
    __syncthreads();

    const int is64d = g_is64_dates, is64l = g_is64_labels;
    long long t      = (long long)blockIdx.x * blockDim.x + threadIdx.x;
    long long stride = (long long)gridDim.x * blockDim.x;
    float acc = 0.f;
    for (long long k = t; k < pairs; k += stride) {
        float4 s = scores[k];
        int d0, d1, l0, l1;
        if (is64d) { longlong2 v = ((const longlong2*)dates)[k];  d0 = (int)v.x; d1 = (int)v.y; }
        else       { int2      v = ((const int2*)dates)[k];       d0 = v.x;      d1 = v.y;      }
        if (is64l) { longlong2 v = ((const longlong2*)labels)[k]; l0 = (int)v.x; l1 = (int)v.y; }
        else       { int2      v = ((const int2*)labels)[k];      l0 = v.x;      l1 = v.y;      }

        float p0 = __fdividef(1.f, 1.f + __expf(s.x - s.y));
        float p1 = __fdividef(1.f, 1.f + __expf(s.z - s.w));
        float2 t0 = tab[d0], t1 = tab[d1];
        acc += (t0.x * (l0 ? E5f : 1.f)) * (t0.y - p0);
        acc += (t1.x * (l1 ? E5f : 1.f)) * (t1.y - p1);
    }
    // block reduce -> one double atomic per block
#pragma unroll
    for (int o = 16; o; o >>= 1) acc += __shfl_down_sync(0xffffffffu, acc, o);
    __shared__ float wsum[T1 / 32];
    if ((threadIdx.x & 31) == 0) wsum[threadIdx.x >> 5] = acc;
    __syncthreads();
    if (threadIdx.x < 32) {
        float v = (threadIdx.x < (T1 / 32)) ? wsum[threadIdx.x] : 0.f;
#pragma unroll
        for (int o = 8; o; o >>= 1) v += __shfl_down_sync(0xffffffffu, v, o);
        if (threadIdx.x == 0) atomicAdd(&g_ce, (double)v);
    }
}

// -------------------------------------------------------------- finalize ----
__global__ void k_final(float* out) {
    if (threadIdx.x == 0) {
        int nv = g_nvalid;
        if (nv < 1) nv = 1;
        out[0] = (float)(g_ce / (double)nv);
    }
}

// ------------------------------------------------------------------ entry ---
extern "C" void kernel_launch(void* const* d_in, const int* in_sizes, int n_in,
                              void* d_out, int out_size) {
    const float* scores = (const float*)d_in[0];
    const void*  labels = d_in[1];
    const void*  dates  = d_in[2];
    long long B     = (long long)in_sizes[1];   // labels element count
    long long pairs = B >> 1;

    k_detect<<<1, 32>>>((const unsigned int*)labels, (const unsigned int*)dates);
    k_init<<<256, 512>>>();
    k_pass1<<<NREP, T1>>>((const float4*)scores, labels, dates, pairs);
    k_reduce<<<NDATES / 256, 256>>>();
    k_pass2<<<NREP, T1>>>((const float4*)scores, labels, dates, pairs);
    k_final<<<1, 32>>>((float*)d_out);
}

// round 2
// speedup vs baseline: 1.0619x; 1.0619x over previous
#include <cuda_runtime.h>

// ListNet ranking loss, GB300 — single-pass formulation.
//
// loss = ( Σ_{valid d} [ logDenomP[d] - (sumP[d] + (e^5-1)*sumPL[d]) / denomT[d] ] ) / nvalid
// where per date d: denomP = Σ exp(p), denomT = cnt + lab*(e^5-1),
//                   sumP = Σ p, sumPL = Σ p·[l==1],  p = sigmoid(s1-s0).
//
// pass: per row, TWO packed u64 REDs into per-block replica slabs (transposed
//       layout [date][replica] for coalesced reduce).
//   word A: bits[0,33)=Σexp(p)·2^16, [33,48)=cnt, [48,63)=lab
//   word B: bits[0,32)=Σp·2^16,      [32,64)=Σp·l·2^16
// reduce: warp per date, coalesced, block-aggregated double atomic.

#define NDATES 4096
#define NREP   304
#define T1     512
#define E5M1f  147.4131591025766f   // e^5 - 1

typedef unsigned long long u64;
typedef unsigned int u32;

__device__ u64    g_pA[(size_t)NDATES * NREP];   // 10MB
__device__ u64    g_pB[(size_t)NDATES * NREP];   // 10MB
__device__ double g_ce;
__device__ int    g_nvalid;
__device__ int    g_is64_dates, g_is64_labels;

// ---------------------------------------------------------------- detect ----
__global__ void k_detect(const u32* __restrict__ labels,
                         const u32* __restrict__ dates) {
    if (threadIdx.x == 0) {
        int d64 = 1, l64 = 1;
#pragma unroll 1
        for (int i = 1; i < 256; i += 2) {
            if (dates[i])  d64 = 0;
            if (labels[i]) l64 = 0;
        }
        g_is64_dates  = d64;
        g_is64_labels = l64;
    }
}

// ------------------------------------------------------------------ init ----
__global__ void k_init() {
    size_t i      = (size_t)blockIdx.x * blockDim.x + threadIdx.x;
    size_t stride = (size_t)gridDim.x * blockDim.x;
    size_t tot    = (size_t)NDATES * NREP;
    for (; i < tot; i += stride) { g_pA[i] = 0ull; g_pB[i] = 0ull; }
    if (blockIdx.x == 0 && threadIdx.x == 0) { g_ce = 0.0; g_nvalid = 0; }
}

// ------------------------------------------------------------------ pass ----
__global__ void __launch_bounds__(T1) k_pass(
        const float4* __restrict__ scores,
        const void*   __restrict__ labels,
        const void*   __restrict__ dates,
        long long pairs) {
    const int is64d = g_is64_dates, is64l = g_is64_labels;
    const int rep   = blockIdx.x;                 // this block's replica column
    long long t      = (long long)blockIdx.x * blockDim.x + threadIdx.x;
    long long stride = (long long)gridDim.x * blockDim.x;
    for (long long k = t; k < pairs; k += stride) {
        float4 s = scores[k];                      // rows 2k, 2k+1
        int d0, d1, l0, l1;
        if (is64d) { longlong2 v = ((const longlong2*)dates)[k];  d0 = (int)v.x; d1 = (int)v.y; }
        else       { int2      v = ((const int2*)dates)[k];       d0 = v.x;      d1 = v.y;      }
        if (is64l) { longlong2 v = ((const longlong2*)labels)[k]; l0 = (int)v.x; l1 = (int)v.y; }
        else       { int2      v = ((const int2*)labels)[k];      l0 = v.x;      l1 = v.y;      }

        float p0 = __fdividef(1.f, 1.f + __expf(s.x - s.y));   // sigmoid(s1-s0)
        float p1 = __fdividef(1.f, 1.f + __expf(s.z - s.w));

        u32 ep0 = __float2uint_rn(__expf(p0) * 65536.f);
        u32 ep1 = __float2uint_rn(__expf(p1) * 65536.f);
        u32 pf0 = __float2uint_rn(p0 * 65536.f);
        u32 pf1 = __float2uint_rn(p1 * 65536.f);

        u64 a0 = (u64)ep0 + (1ull << 33) + ((u64)(l0 != 0) << 48);
        u64 a1 = (u64)ep1 + (1ull << 33) + ((u64)(l1 != 0) << 48);
        u64 b0 = (u64)pf0 | ((u64)(l0 ? pf0 : 0u) << 32);
        u64 b1 = (u64)pf1 | ((u64)(l1 ? pf1 : 0u) << 32);

        size_t o0 = (size_t)d0 * NREP + rep;
        size_t o1 = (size_t)d1 * NREP + rep;
        atomicAdd(g_pA + o0, a0);
        atomicAdd(g_pB + o0, b0);
        atomicAdd(g_pA + o1, a1);
        atomicAdd(g_pB + o1, b1);
    }
}

// ---------------------------------------------------------------- reduce ----
// One warp per date; lanes stream the contiguous [NREP] replica row.
__global__ void k_reduce() {
    const int warp = threadIdx.x >> 5;
    const int lane = threadIdx.x & 31;
    const int d    = blockIdx.x * 4 + warp;        // 1024 blocks * 4 warps
    const size_t base = (size_t)d * NREP;

    u64 epsum = 0, spfx = 0, splfx = 0;
    u32 cnt = 0, lab = 0;
    for (int r = lane; r < NREP; r += 32) {
        u64 va = g_pA[base + r];
        u64 vb = g_pB[base + r];
        epsum += va & ((1ull << 33) - 1);
        cnt   += (u32)((va >> 33) & 0x7FFFu);
        lab   += (u32)(va >> 48);
        spfx  += vb & 0xFFFFFFFFull;
        splfx += vb >> 32;
    }
#pragma unroll
    for (int o = 16; o; o >>= 1) {
        epsum += __shfl_down_sync(0xffffffffu, epsum, o);
        spfx  += __shfl_down_sync(0xffffffffu, spfx,  o);
        splfx += __shfl_down_sync(0xffffffffu, splfx, o);
        cnt   += __shfl_down_sync(0xffffffffu, cnt,   o);
        lab   += __shfl_down_sync(0xffffffffu, lab,   o);
    }

    __shared__ double s_ce[4];
    __shared__ int    s_nv[4];
    if (lane == 0) {
        bool valid = (cnt >= 2);
        double ce = 0.0;
        if (valid) {
            float denomT = (float)cnt + (float)lab * E5M1f;
            float sumP   = (float)spfx  * (1.f / 65536.f);
            float sumPL  = (float)splfx * (1.f / 65536.f);
            float logD   = __logf((float)epsum * (1.f / 65536.f));
            ce = (double)(logD - (sumP + E5M1f * sumPL) / denomT);
        }
        s_ce[warp] = ce;
        s_nv[warp] = valid ? 1 : 0;
    }
    __syncthreads();
    if (threadIdx.x == 0) {
        double ce = s_ce[0] + s_ce[1] + s_ce[2] + s_ce[3];
        int    nv = s_nv[0] + s_nv[1] + s_nv[2] + s_nv[3];
        atomicAdd(&g_ce, ce);
        atomicAdd(&g_nvalid, nv);
    }
}

// -------------------------------------------------------------- finalize ----
__global__ void k_final(float* out) {
    if (threadIdx.x == 0) {
        int nv = g_nvalid;
        if (nv < 1) nv = 1;
        out[0] = (float)(g_ce / (double)nv);
    }
}

// ------------------------------------------------------------------ entry ---
extern "C" void kernel_launch(void* const* d_in, const int* in_sizes, int n_in,
                              void* d_out, int out_size) {
    const float* scores = (const float*)d_in[0];
    const void*  labels = d_in[1];
    const void*  dates  = d_in[2];
    long long B     = (long long)in_sizes[1];
    long long pairs = B >> 1;

    k_detect<<<1, 32>>>((const u32*)labels, (const u32*)dates);
    k_init<<<512, 512>>>();
    k_pass<<<NREP, T1>>>((const float4*)scores, labels, dates, pairs);
    k_reduce<<<NDATES / 4, 128>>>();
    k_final<<<1, 32>>>((float*)d_out);
}

// round 3
// speedup vs baseline: 1.5280x; 1.4390x over previous
#include <cuda_runtime.h>

// ListNet ranking loss, GB300 — single pass, ONE v4.f32 RED per row.
//
// loss = ( Σ_{valid d} [ log(ΣexpP[d]) - (sumP[d] + (e^5-1)*sumPL[d]) / denomT[d] ] ) / nvalid
//   denomT = cnt + lab*(e^5-1),  p = sigmoid(s1-s0)
//
// Per-block replica slab g_part[date][NREP] of float4 {expP, p, p*l, w}
// where w = 1 + l*2^-13 packs (cnt, lab): exact while per-slab cnt < 1024
// (actual per-cell Poisson mean ~6.7). Fold across replicas in double.

#define NDATES 4096
#define NREP   304
#define T1     512
#define E5M1f  147.4131591025766f   // e^5 - 1
#define LPK    1.220703125e-4f      // 2^-13

typedef unsigned long long u64;
typedef unsigned int u32;

__device__ float4 g_part[(size_t)NDATES * NREP];   // 20MB scratch
__device__ double g_ce;
__device__ int    g_nvalid;
__device__ int    g_is64_dates, g_is64_labels;

__device__ __forceinline__ void red_v4(float4* p, float a, float b, float c, float d) {
    asm volatile("red.global.add.v4.f32 [%0], {%1,%2,%3,%4};"
                 :: "l"(p), "f"(a), "f"(b), "f"(c), "f"(d) : "memory");
}

// ---------------------------------------------------------------- detect ----
// int64 vs int32 sniff: values < 4096, so int64 => every odd 32-bit word == 0.
__global__ void k_detect(const u32* __restrict__ labels,
                         const u32* __restrict__ dates) {
    int lane = threadIdx.x;
    u32 dv = 0, lv = 0;
#pragma unroll
    for (int i = 0; i < 8; i++) {
        int idx = 1 + 2 * (lane + 32 * i);   // odd words 1..1023
        dv |= dates[idx];
        lv |= labels[idx];
    }
    u32 dm = __ballot_sync(0xffffffffu, dv != 0);
    u32 lm = __ballot_sync(0xffffffffu, lv != 0);
    if (lane == 0) {
        g_is64_dates  = (dm == 0);
        g_is64_labels = (lm == 0);
        g_ce = 0.0;
        g_nvalid = 0;
    }
}

// ------------------------------------------------------------------ pass ----
__global__ void __launch_bounds__(T1) k_pass(
        const float4* __restrict__ scores,
        const void*   __restrict__ labels,
        const void*   __restrict__ dates,
        long long pairs) {
    const int rep = blockIdx.x;

    // Zero this block's replica column (only this block REDs into it).
    for (int d = threadIdx.x; d < NDATES; d += T1)
        g_part[(size_t)d * NREP + rep] = make_float4(0.f, 0.f, 0.f, 0.f);
    __syncthreads();

    const int is64d = g_is64_dates, is64l = g_is64_labels;
    long long t      = (long long)blockIdx.x * blockDim.x + threadIdx.x;
    long long stride = (long long)gridDim.x * blockDim.x;
    for (long long k = t; k < pairs; k += stride) {
        float4 s = scores[k];                      // rows 2k, 2k+1
        int d0, d1, l0, l1;
        if (is64d) { longlong2 v = ((const longlong2*)dates)[k];  d0 = (int)v.x; d1 = (int)v.y; }
        else       { int2      v = ((const int2*)dates)[k];       d0 = v.x;      d1 = v.y;      }
        if (is64l) { longlong2 v = ((const longlong2*)labels)[k]; l0 = (int)v.x; l1 = (int)v.y; }
        else       { int2      v = ((const int2*)labels)[k];      l0 = v.x;      l1 = v.y;      }

        float p0 = __fdividef(1.f, 1.f + __expf(s.x - s.y));   // sigmoid(s1-s0)
        float p1 = __fdividef(1.f, 1.f + __expf(s.z - s.w));
        float e0 = __expf(p0), e1 = __expf(p1);

        red_v4(g_part + (size_t)d0 * NREP + rep,
               e0, p0, l0 ? p0 : 0.f, l0 ? (1.f + LPK) : 1.f);
        red_v4(g_part + (size_t)d1 * NREP + rep,
               e1, p1, l1 ? p1 : 0.f, l1 ? (1.f + LPK) : 1.f);
    }
}

// ---------------------------------------------------------------- reduce ----
// One warp per date; lanes stream the contiguous [NREP] float4 row.
__global__ void k_reduce() {
    const int warp = threadIdx.x >> 5;
    const int lane = threadIdx.x & 31;
    const int d    = blockIdx.x * 8 + warp;        // 512 blocks * 8 warps
    const size_t base = (size_t)d * NREP;

    float ep = 0.f, sp = 0.f, spl = 0.f, w = 0.f;
    for (int r = lane; r < NREP; r += 32) {
        float4 v = g_part[base + r];
        ep  += v.x;
        sp  += v.y;
        spl += v.z;
        w   += v.w;
    }
    double dep = ep, dsp = sp, dspl = spl, dw = w;
#pragma unroll
    for (int o = 16; o; o >>= 1) {
        dep  += __shfl_down_sync(0xffffffffu, dep,  o);
        dsp  += __shfl_down_sync(0xffffffffu, dsp,  o);
        dspl += __shfl_down_sync(0xffffffffu, dspl, o);
        dw   += __shfl_down_sync(0xffffffffu, dw,   o);
    }

    __shared__ double s_ce[8];
    __shared__ int    s_nv[8];
    if (lane == 0) {
        int cnt = (int)dw;                          // exact: dw = cnt + lab*2^-13
        int lab = (int)((dw - (double)cnt) * 8192.0 + 0.5);
        bool valid = (cnt >= 2);
        double ce = 0.0;
        if (valid) {
            float denomT = (float)cnt + (float)lab * E5M1f;
            float logD   = __logf((float)dep);
            ce = (double)(logD - ((float)dsp + E5M1f * (float)dspl) / denomT);
        }
        s_ce[warp] = ce;
        s_nv[warp] = valid ? 1 : 0;
    }
    __syncthreads();
    if (threadIdx.x == 0) {
        double ce = 0.0; int nv = 0;
#pragma unroll
        for (int i = 0; i < 8; i++) { ce += s_ce[i]; nv += s_nv[i]; }
        atomicAdd(&g_ce, ce);
        atomicAdd(&g_nvalid, nv);
    }
}

// -------------------------------------------------------------- finalize ----
__global__ void k_final(float* out) {
    int nv = g_nvalid;
    if (nv < 1) nv = 1;
    out[0] = (float)(g_ce / (double)nv);
}

// ------------------------------------------------------------------ entry ---
extern "C" void kernel_launch(void* const* d_in, const int* in_sizes, int n_in,
                              void* d_out, int out_size) {
    const float* scores = (const float*)d_in[0];
    const void*  labels = d_in[1];
    const void*  dates  = d_in[2];
    long long B     = (long long)in_sizes[1];
    long long pairs = B >> 1;

    k_detect<<<1, 32>>>((const u32*)labels, (const u32*)dates);
    k_pass<<<NREP, T1>>>((const float4*)scores, labels, dates, pairs);
    k_reduce<<<NDATES / 8, 256>>>();
    k_final<<<1, 1>>>((float*)d_out);
}